// round 3
// baseline (speedup 1.0000x reference)
#include <cuda_runtime.h>
#include <math.h>

#define B        512
#define IN       1024
#define NN       4224
#define TOTAL    5248
#define KB       128
#define NBLK     33
#define OUT_N    128

// Scratch (device globals: allocation-free rule)
__device__ float g_pre[(size_t)B * NN];   // preactivations [row][node]
__device__ float g_h[(size_t)B * KB];     // current block outputs [row][t]

// ---------------------------------------------------------------------------
// Tiled fp32 GEMM:  C[r][jbase+n] (+)= sum_k A[r][k] * Wsub[n*TOTAL + k]
// M=512 fixed, BM=BN=64, BK=16, 256 threads, 4x4 microtile.
// asel: 0 -> A = Aparam (x), 1 -> A = g_h.
// ---------------------------------------------------------------------------
#define BM 64
#define BN 64
#define BK 16

__global__ void gemm_kernel(const float* __restrict__ Aparam, int lda,
                            const float* __restrict__ Wsub,
                            int jbase, int kc, int accum, int asel)
{
    __shared__ float As[BK][BM];
    __shared__ float Bs[BK][BN];

    const float* A = asel ? g_h : Aparam;

    int m0 = blockIdx.x * BM;
    int n0 = blockIdx.y * BN;
    int tid = threadIdx.x;
    int tx = tid & 15;          // 0..15 (n dir)
    int ty = tid >> 4;          // 0..15 (m dir)

    int lr = tid >> 2;          // 0..63
    int lk = (tid & 3) * 4;     // 0,4,8,12

    float acc[4][4];
#pragma unroll
    for (int i = 0; i < 4; i++)
#pragma unroll
        for (int j = 0; j < 4; j++) acc[i][j] = 0.0f;

    for (int kk = 0; kk < kc; kk += BK) {
        float4 av = *(const float4*)(A + (size_t)(m0 + lr) * lda + kk + lk);
        As[lk + 0][lr] = av.x;
        As[lk + 1][lr] = av.y;
        As[lk + 2][lr] = av.z;
        As[lk + 3][lr] = av.w;

        float4 bv = *(const float4*)(Wsub + (size_t)(n0 + lr) * TOTAL + kk + lk);
        Bs[lk + 0][lr] = bv.x;
        Bs[lk + 1][lr] = bv.y;
        Bs[lk + 2][lr] = bv.z;
        Bs[lk + 3][lr] = bv.w;

        __syncthreads();

#pragma unroll
        for (int k = 0; k < BK; k++) {
            float a[4], b[4];
            *(float4*)a = *(const float4*)&As[k][ty * 4];
            *(float4*)b = *(const float4*)&Bs[k][tx * 4];
#pragma unroll
            for (int mm = 0; mm < 4; mm++)
#pragma unroll
                for (int nn = 0; nn < 4; nn++)
                    acc[mm][nn] += a[mm] * b[nn];
        }
        __syncthreads();
    }

#pragma unroll
    for (int mm = 0; mm < 4; mm++) {
        float* cp = g_pre + (size_t)(m0 + ty * 4 + mm) * NN + jbase + n0 + tx * 4;
        if (accum) {
#pragma unroll
            for (int nn = 0; nn < 4; nn++) cp[nn] += acc[mm][nn];
        } else {
            float4 v;
            v.x = acc[mm][0]; v.y = acc[mm][1]; v.z = acc[mm][2]; v.w = acc[mm][3];
            *(float4*)cp = v;
        }
    }
}

// ---------------------------------------------------------------------------
// In-block sequential recurrence. One warp per batch row (64 blocks x 8
// warps = 512 rows). Lane owns nodes node = lane + 32q, q=0..3.
//
// Per-step critical path:
//   FMUL -> ex2.approx -> FADD -> rcp.approx -> FMA -> SHFL -> FMA  ~74 cyc.
// tanh(p) = 1 - 2/(exp(2p)+1): safe at +/-inf (rcp(inf)=0 -> 1).
// No branches in the loop; single coalesced publish after the loop.
//
// smem: ws[i*129 + t] = W[j0+i][IN+j0+t]. Stride 129 (odd) makes the inner
// reads ws[node*129 + t] bank-conflict-free across lanes. Odd stride forbids
// vector STS, so staging is scalar: t in the lane direction gives coalesced
// LDG.32 and conflict-free STS ((129i+t) mod 32 = (i+lane) mod 32).
// ---------------------------------------------------------------------------
__global__ void seq_kernel(const float* __restrict__ W,
                           float* __restrict__ out, int b)
{
    extern __shared__ float ws[];  // 128*129 floats = 66048 B

    int tid  = threadIdx.x;        // 256
    int lane = tid & 31;
    int row  = blockIdx.x * 8 + (tid >> 5);
    int j0   = b * KB;

    // Stage triangular weight tile (scalar, coalesced, conflict-free).
    {
        const float* Wt = W + (size_t)j0 * TOTAL + IN + j0;
#pragma unroll 8
        for (int idx = tid; idx < KB * KB; idx += 256) {
            int i = idx >> 7;      // node within block
            int t = idx & 127;     // parent within block
            ws[i * 129 + t] = Wt[(size_t)i * TOTAL + t];
        }
    }
    __syncthreads();

    float p[4];
#pragma unroll
    for (int q = 0; q < 4; q++)
        p[q] = g_pre[(size_t)row * NN + j0 + lane + 32 * q];

    const bool isOut = (b == NBLK - 1);
    float myh[4];

#pragma unroll
    for (int slot = 0; slot < 4; slot++) {
        float own = 0.0f;
#pragma unroll 8
        for (int t2 = 0; t2 < 32; t2++) {
            int t = slot * 32 + t2;

            // tanh via approx ex2 + rcp (few-ulp error; large margin).
            float z = p[slot] * 2.8853900817779268f;   // 2*log2(e)
            float e;  asm("ex2.approx.f32 %0, %1;" : "=f"(e) : "f"(z));
            float d = e + 1.0f;
            float r;  asm("rcp.approx.f32 %0, %1;" : "=f"(r) : "f"(d));
            float hv = fmaf(-2.0f, r, 1.0f);

            own = (lane == t2) ? hv : own;             // select, no branch
            float h = __shfl_sync(0xffffffffu, hv, t2);

#pragma unroll
            for (int q = 0; q < 4; q++) {
                int node = lane + 32 * q;
                float w = ws[node * 129 + t];
                if (node > t) p[q] = fmaf(h, w, p[q]);
            }
        }
        myh[slot] = own;
    }

    // Publish once, coalesced.
    if (!isOut) {
        float* ghrow = g_h + (size_t)row * KB;
#pragma unroll
        for (int slot = 0; slot < 4; slot++)
            ghrow[slot * 32 + lane] = myh[slot];
    } else {
        float* orow = out + (size_t)row * OUT_N;
#pragma unroll
        for (int slot = 0; slot < 4; slot++)
            orow[slot * 32 + lane] = 1.0f / (1.0f + __expf(-myh[slot]));
    }
}

// ---------------------------------------------------------------------------
extern "C" void kernel_launch(void* const* d_in, const int* in_sizes, int n_in,
                              void* d_out, int out_size)
{
    const float* x = (const float*)d_in[0];   // [512][1024]
    const float* W = (const float*)d_in[1];   // [4224][5248]
    float* out = (float*)d_out;               // [512][128]

    (void)in_sizes; (void)n_in; (void)out_size;

    cudaFuncSetAttribute(seq_kernel,
                         cudaFuncAttributeMaxDynamicSharedMemorySize, 66048);

    // Phase A: pre = x @ W[:, :1024]^T    (writes all of g_pre)
    gemm_kernel<<<dim3(8, NN / BN), 256>>>(x, IN, W, /*jbase=*/0,
                                           /*kc=*/IN, /*accum=*/0, /*asel=*/0);

    for (int b = 0; b < NBLK; b++) {
        seq_kernel<<<64, 256, 66048>>>(W, out, b);

        if (b < NBLK - 1) {
            int jbase = (b + 1) * KB;
            int nrem  = NN - jbase;               // multiple of 128
            const float* Wsub = W + (size_t)jbase * TOTAL + (IN + b * KB);
            gemm_kernel<<<dim3(8, nrem / BN), 256>>>(nullptr, KB, Wsub,
                                                     jbase, KB, /*accum=*/1,
                                                     /*asel=*/1);
        }
    }
}

// round 4
// speedup vs baseline: 1.1764x; 1.1764x over previous
#include <cuda_runtime.h>
#include <math.h>

#define B        512
#define IN       1024
#define NN       4224
#define TOTAL    5248
#define KB       128
#define NBLK     33
#define OUT_N    128

// Scratch (device globals: allocation-free rule)
__device__ float g_pre[(size_t)B * NN];   // preactivations [row][node]
__device__ float g_h[(size_t)B * KB];     // current block outputs [row][t]

// ---------------------------------------------------------------------------
// Tiled fp32 GEMM:  C[r][jbase+n] (+)= sum_k A[r][k] * Wsub[n*TOTAL + k]
// M=512 fixed, BM=BN=64, BK=16, 256 threads, 4x4 microtile.
// ---------------------------------------------------------------------------
#define BM 64
#define BN 64
#define BK 16

__global__ void gemm_kernel(const float* __restrict__ Aparam, int lda,
                            const float* __restrict__ Wsub,
                            int jbase, int kc, int accum, int asel)
{
    __shared__ float As[BK][BM];
    __shared__ float Bs[BK][BN];

    const float* A = asel ? g_h : Aparam;

    int m0 = blockIdx.x * BM;
    int n0 = blockIdx.y * BN;
    int tid = threadIdx.x;
    int tx = tid & 15;
    int ty = tid >> 4;

    int lr = tid >> 2;
    int lk = (tid & 3) * 4;

    float acc[4][4];
#pragma unroll
    for (int i = 0; i < 4; i++)
#pragma unroll
        for (int j = 0; j < 4; j++) acc[i][j] = 0.0f;

    for (int kk = 0; kk < kc; kk += BK) {
        float4 av = *(const float4*)(A + (size_t)(m0 + lr) * lda + kk + lk);
        As[lk + 0][lr] = av.x;
        As[lk + 1][lr] = av.y;
        As[lk + 2][lr] = av.z;
        As[lk + 3][lr] = av.w;

        float4 bv = *(const float4*)(Wsub + (size_t)(n0 + lr) * TOTAL + kk + lk);
        Bs[lk + 0][lr] = bv.x;
        Bs[lk + 1][lr] = bv.y;
        Bs[lk + 2][lr] = bv.z;
        Bs[lk + 3][lr] = bv.w;

        __syncthreads();

#pragma unroll
        for (int k = 0; k < BK; k++) {
            float a[4], b[4];
            *(float4*)a = *(const float4*)&As[k][ty * 4];
            *(float4*)b = *(const float4*)&Bs[k][tx * 4];
#pragma unroll
            for (int mm = 0; mm < 4; mm++)
#pragma unroll
                for (int nn = 0; nn < 4; nn++)
                    acc[mm][nn] += a[mm] * b[nn];
        }
        __syncthreads();
    }

#pragma unroll
    for (int mm = 0; mm < 4; mm++) {
        float* cp = g_pre + (size_t)(m0 + ty * 4 + mm) * NN + jbase + n0 + tx * 4;
        if (accum) {
#pragma unroll
            for (int nn = 0; nn < 4; nn++) cp[nn] += acc[mm][nn];
        } else {
            float4 v;
            v.x = acc[mm][0]; v.y = acc[mm][1]; v.z = acc[mm][2]; v.w = acc[mm][3];
            *(float4*)cp = v;
        }
    }
}

// ---------------------------------------------------------------------------
// In-block sequential recurrence, v3: 16 blocks x 1024 threads (32 warps),
// one warp per batch row. 8 warps/SMSP hide scoreboard latency; the kernel
// is issue-bound, so instructions/step are minimized:
//  - weight tile zeroed at t >= i  -> unconditional FMAs (no predicates)
//  - slot s inner loop runs q = s..3 (earlier slots finalized)
//  - own-h: p[q] is final after node q's own step; tanh once after the loop
// Per step: FMUL,EX2,FADD,RCP,FMA (tanh) + SHFL + (4-s)x(LDS+FMA).
//
// smem ws[i*129 + t]: odd stride -> conflict-free reads; scalar staging is
// coalesced (t in lane direction) and conflict-free STS.
// ---------------------------------------------------------------------------
__global__ void __launch_bounds__(1024, 1)
seq_kernel(const float* __restrict__ W, float* __restrict__ out, int b)
{
    extern __shared__ float ws[];  // 128*129 floats = 66048 B

    int tid  = threadIdx.x;        // 1024
    int lane = tid & 31;
    int row  = blockIdx.x * 32 + (tid >> 5);
    int j0   = b * KB;

    // Stage triangular tile; zero t >= i (padded entries -> inert).
    {
        const float* Wt = W + (size_t)j0 * TOTAL + IN + j0;
#pragma unroll
        for (int ii = 0; ii < 16; ii++) {
            int idx = tid + ii * 1024;
            int i = idx >> 7;      // node within block
            int t = idx & 127;     // parent within block
            float v = Wt[(size_t)i * TOTAL + t];
            ws[i * 129 + t] = (t < i) ? v : 0.0f;
        }
    }
    __syncthreads();

    float p[4];
#pragma unroll
    for (int q = 0; q < 4; q++)
        p[q] = g_pre[(size_t)row * NN + j0 + lane + 32 * q];

    const float* wbase = ws + lane * 129;   // + q*32*129 + t

#pragma unroll
    for (int slot = 0; slot < 4; slot++) {
#pragma unroll
        for (int t2 = 0; t2 < 32; t2++) {
            int t = slot * 32 + t2;

            // tanh(p) = 1 - 2/(exp(2p)+1), approx ex2+rcp (few-ulp error).
            float z = p[slot] * 2.8853900817779268f;   // 2*log2(e)
            float e;  asm("ex2.approx.f32 %0, %1;" : "=f"(e) : "f"(z));
            float d = e + 1.0f;
            float r;  asm("rcp.approx.f32 %0, %1;" : "=f"(r) : "f"(d));
            float hv = fmaf(-2.0f, r, 1.0f);

            float h = __shfl_sync(0xffffffffu, hv, t2);

#pragma unroll
            for (int q = slot; q < 4; q++)
                p[q] = fmaf(h, wbase[q * 32 * 129 + t], p[q]);
        }
    }

    // Finalize: p[q] holds the final preactivation of node lane+32q.
    const bool isOut = (b == NBLK - 1);
    if (!isOut) {
        float* ghrow = g_h + (size_t)row * KB;
#pragma unroll
        for (int q = 0; q < 4; q++) {
            float z = p[q] * 2.8853900817779268f;
            float e;  asm("ex2.approx.f32 %0, %1;" : "=f"(e) : "f"(z));
            float d = e + 1.0f;
            float r;  asm("rcp.approx.f32 %0, %1;" : "=f"(r) : "f"(d));
            ghrow[q * 32 + lane] = fmaf(-2.0f, r, 1.0f);
        }
    } else {
        float* orow = out + (size_t)row * OUT_N;
#pragma unroll
        for (int q = 0; q < 4; q++) {
            float z = p[q] * 2.8853900817779268f;
            float e;  asm("ex2.approx.f32 %0, %1;" : "=f"(e) : "f"(z));
            float d = e + 1.0f;
            float r;  asm("rcp.approx.f32 %0, %1;" : "=f"(r) : "f"(d));
            float h = fmaf(-2.0f, r, 1.0f);
            orow[q * 32 + lane] = 1.0f / (1.0f + __expf(-h));
        }
    }
}

// ---------------------------------------------------------------------------
extern "C" void kernel_launch(void* const* d_in, const int* in_sizes, int n_in,
                              void* d_out, int out_size)
{
    const float* x = (const float*)d_in[0];   // [512][1024]
    const float* W = (const float*)d_in[1];   // [4224][5248]
    float* out = (float*)d_out;               // [512][128]

    (void)in_sizes; (void)n_in; (void)out_size;

    cudaFuncSetAttribute(seq_kernel,
                         cudaFuncAttributeMaxDynamicSharedMemorySize, 66048);

    // Phase A: pre = x @ W[:, :1024]^T    (writes all of g_pre)
    gemm_kernel<<<dim3(8, NN / BN), 256>>>(x, IN, W, /*jbase=*/0,
                                           /*kc=*/IN, /*accum=*/0, /*asel=*/0);

    for (int b = 0; b < NBLK; b++) {
        seq_kernel<<<16, 1024, 66048>>>(W, out, b);

        if (b < NBLK - 1) {
            int jbase = (b + 1) * KB;
            int nrem  = NN - jbase;               // multiple of 128
            const float* Wsub = W + (size_t)jbase * TOTAL + (IN + b * KB);
            gemm_kernel<<<dim3(8, nrem / BN), 256>>>(nullptr, KB, Wsub,
                                                     jbase, KB, /*accum=*/1,
                                                     /*asel=*/1);
        }
    }
}

// round 5
// speedup vs baseline: 1.2737x; 1.0827x over previous
#include <cuda_runtime.h>
#include <math.h>

#define B        512
#define IN       1024
#define NN       4224
#define TOTAL    5248
#define KB       128
#define NBLK     33
#define OUT_N    128

// Scratch (device globals: allocation-free rule)
__device__ float g_pre[(size_t)B * NN];   // preactivations [row][node]
__device__ float g_h[(size_t)B * KB];     // current block outputs [row][t]

// ---------------------------------------------------------------------------
// Tiled fp32 GEMM:  C[r][jbase+n] (+)= sum_k A[r][k] * Wsub[n*TOTAL + k]
// BM=128, BN=64, BK=16, 256 threads, 8x4 microtile.
// Smem strides padded (132 / 68) -> conflict-free LDS.128 in the hot loop.
// ---------------------------------------------------------------------------
#define BM 128
#define BN 64
#define BK 16
#define AS 132
#define BS 68

__global__ void __launch_bounds__(256)
gemm_kernel(const float* __restrict__ Aparam, int lda,
            const float* __restrict__ Wsub,
            int jbase, int kc, int accum, int asel)
{
    __shared__ float As[BK * AS];
    __shared__ float Bs[BK * BS];

    const float* A = asel ? g_h : Aparam;

    int m0 = blockIdx.x * BM;
    int n0 = blockIdx.y * BN;
    int tid = threadIdx.x;
    int tx = tid & 15;          // n dir: 4 cols each
    int ty = tid >> 4;          // m dir: 8 rows each

    // A staging map: 128 rows x 16 k, 8 floats/thread (two float4)
    int a_r = tid >> 1;           // 0..127
    int a_k = (tid & 1) * 8;      // 0 or 8
    // B staging map: 64 rows x 16 k, 4 floats/thread (one float4)
    int b_r = tid >> 2;           // 0..63
    int b_k = (tid & 3) * 4;      // 0,4,8,12

    float acc[8][4];
#pragma unroll
    for (int i = 0; i < 8; i++)
#pragma unroll
        for (int j = 0; j < 4; j++) acc[i][j] = 0.0f;

    for (int kk = 0; kk < kc; kk += BK) {
        float4 a0 = *(const float4*)(A + (size_t)(m0 + a_r) * lda + kk + a_k);
        float4 a1 = *(const float4*)(A + (size_t)(m0 + a_r) * lda + kk + a_k + 4);
        As[(a_k + 0) * AS + a_r] = a0.x;
        As[(a_k + 1) * AS + a_r] = a0.y;
        As[(a_k + 2) * AS + a_r] = a0.z;
        As[(a_k + 3) * AS + a_r] = a0.w;
        As[(a_k + 4) * AS + a_r] = a1.x;
        As[(a_k + 5) * AS + a_r] = a1.y;
        As[(a_k + 6) * AS + a_r] = a1.z;
        As[(a_k + 7) * AS + a_r] = a1.w;

        float4 bv = *(const float4*)(Wsub + (size_t)(n0 + b_r) * TOTAL + kk + b_k);
        Bs[(b_k + 0) * BS + b_r] = bv.x;
        Bs[(b_k + 1) * BS + b_r] = bv.y;
        Bs[(b_k + 2) * BS + b_r] = bv.z;
        Bs[(b_k + 3) * BS + b_r] = bv.w;

        __syncthreads();

#pragma unroll
        for (int k = 0; k < BK; k++) {
            float a[8], b[4];
            *(float4*)&a[0] = *(const float4*)&As[k * AS + ty * 8];
            *(float4*)&a[4] = *(const float4*)&As[k * AS + ty * 8 + 4];
            *(float4*)&b[0] = *(const float4*)&Bs[k * BS + tx * 4];
#pragma unroll
            for (int mm = 0; mm < 8; mm++)
#pragma unroll
                for (int nn = 0; nn < 4; nn++)
                    acc[mm][nn] = fmaf(a[mm], b[nn], acc[mm][nn]);
        }
        __syncthreads();
    }

#pragma unroll
    for (int mm = 0; mm < 8; mm++) {
        float* cp = g_pre + (size_t)(m0 + ty * 8 + mm) * NN + jbase + n0 + tx * 4;
        if (accum) {
#pragma unroll
            for (int nn = 0; nn < 4; nn++) cp[nn] += acc[mm][nn];
        } else {
            float4 v;
            v.x = acc[mm][0]; v.y = acc[mm][1]; v.z = acc[mm][2]; v.w = acc[mm][3];
            *(float4*)cp = v;
        }
    }
}

// ---------------------------------------------------------------------------
// In-block sequential recurrence, v4: 32 CTAs x 512 threads (16 warps),
// one warp per batch row. 4 warps/SMSP: MUFU pipe load (2 MUFU/step/warp x
// rt8 = 64 cyc/step) now sits UNDER the ~75 cyc dependency chain, so the
// kernel runs at chain speed instead of MUFU saturation (the round-3
// config at 8 warps/SMSP was MUFU-bound at ~110 cyc/step).
//  - weight tile zeroed at t >= i -> unconditional FMAs
//  - slot s inner loop runs q = s..3
//  - own-h recomputed once after the loop (p[q] final after own step)
// smem ws[i*129 + t]: odd stride -> conflict-free reads; scalar staging.
// ---------------------------------------------------------------------------
__global__ void __launch_bounds__(512, 1)
seq_kernel(const float* __restrict__ W, float* __restrict__ out, int b)
{
    extern __shared__ float ws[];  // 128*129 floats = 66048 B

    int tid  = threadIdx.x;        // 512
    int lane = tid & 31;
    int row  = blockIdx.x * 16 + (tid >> 5);
    int j0   = b * KB;

    // Stage triangular tile; zero t >= i (padded entries -> inert).
    {
        const float* Wt = W + (size_t)j0 * TOTAL + IN + j0;
#pragma unroll
        for (int ii = 0; ii < 32; ii++) {
            int idx = tid + ii * 512;
            int i = idx >> 7;      // node within block
            int t = idx & 127;     // parent within block
            float v = Wt[(size_t)i * TOTAL + t];
            ws[i * 129 + t] = (t < i) ? v : 0.0f;
        }
    }
    __syncthreads();

    float p[4];
#pragma unroll
    for (int q = 0; q < 4; q++)
        p[q] = g_pre[(size_t)row * NN + j0 + lane + 32 * q];

    const float* wbase = ws + lane * 129;   // + q*32*129 + t

#pragma unroll
    for (int slot = 0; slot < 4; slot++) {
#pragma unroll
        for (int t2 = 0; t2 < 32; t2++) {
            int t = slot * 32 + t2;

            // tanh(p) = 1 - 2/(exp(2p)+1), approx ex2+rcp (few-ulp error).
            float z = p[slot] * 2.8853900817779268f;   // 2*log2(e)
            float e;  asm("ex2.approx.f32 %0, %1;" : "=f"(e) : "f"(z));
            float d = e + 1.0f;
            float r;  asm("rcp.approx.f32 %0, %1;" : "=f"(r) : "f"(d));
            float hv = fmaf(-2.0f, r, 1.0f);

            float h = __shfl_sync(0xffffffffu, hv, t2);

#pragma unroll
            for (int q = slot; q < 4; q++)
                p[q] = fmaf(h, wbase[q * 32 * 129 + t], p[q]);
        }
    }

    // Finalize: p[q] holds the final preactivation of node lane+32q.
    const bool isOut = (b == NBLK - 1);
    if (!isOut) {
        float* ghrow = g_h + (size_t)row * KB;
#pragma unroll
        for (int q = 0; q < 4; q++) {
            float z = p[q] * 2.8853900817779268f;
            float e;  asm("ex2.approx.f32 %0, %1;" : "=f"(e) : "f"(z));
            float d = e + 1.0f;
            float r;  asm("rcp.approx.f32 %0, %1;" : "=f"(r) : "f"(d));
            ghrow[q * 32 + lane] = fmaf(-2.0f, r, 1.0f);
        }
    } else {
        float* orow = out + (size_t)row * OUT_N;
#pragma unroll
        for (int q = 0; q < 4; q++) {
            float z = p[q] * 2.8853900817779268f;
            float e;  asm("ex2.approx.f32 %0, %1;" : "=f"(e) : "f"(z));
            float d = e + 1.0f;
            float r;  asm("rcp.approx.f32 %0, %1;" : "=f"(r) : "f"(d));
            float h = fmaf(-2.0f, r, 1.0f);
            orow[q * 32 + lane] = 1.0f / (1.0f + __expf(-h));
        }
    }
}

// ---------------------------------------------------------------------------
extern "C" void kernel_launch(void* const* d_in, const int* in_sizes, int n_in,
                              void* d_out, int out_size)
{
    const float* x = (const float*)d_in[0];   // [512][1024]
    const float* W = (const float*)d_in[1];   // [4224][5248]
    float* out = (float*)d_out;               // [512][128]

    (void)in_sizes; (void)n_in; (void)out_size;

    cudaFuncSetAttribute(seq_kernel,
                         cudaFuncAttributeMaxDynamicSharedMemorySize, 66048);

    // Phase A: pre = x @ W[:, :1024]^T    (writes all of g_pre)
    gemm_kernel<<<dim3(B / BM, NN / BN), 256>>>(x, IN, W, /*jbase=*/0,
                                                /*kc=*/IN, /*accum=*/0,
                                                /*asel=*/0);

    for (int b = 0; b < NBLK; b++) {
        seq_kernel<<<32, 512, 66048>>>(W, out, b);

        if (b < NBLK - 1) {
            int jbase = (b + 1) * KB;
            int nrem  = NN - jbase;               // multiple of 128
            const float* Wsub = W + (size_t)jbase * TOTAL + (IN + b * KB);
            gemm_kernel<<<dim3(B / BM, nrem / BN), 256>>>(nullptr, KB, Wsub,
                                                          jbase, KB,
                                                          /*accum=*/1,
                                                          /*asel=*/1);
        }
    }
}

// round 6
// speedup vs baseline: 1.3209x; 1.0371x over previous
#include <cuda_runtime.h>
#include <math.h>

#define B        512
#define IN       1024
#define NN       4224
#define TOTAL    5248
#define KB       128
#define NBLK     33
#define OUT_N    128

// Scratch (device globals: allocation-free rule)
__device__ float g_pre[(size_t)B * NN];   // preactivations [row][node]
__device__ float g_h[(size_t)B * KB];     // current block outputs [row][t]

// ---------------------------------------------------------------------------
// Tiled fp32 GEMM on the packed f32x2 pipe (fma.rn.f32x2 = FFMA2, 2 FMA/instr,
// ~2x scalar FFMA throughput; scalar FFMA was measured at the rt=2 ceiling).
// C[r][jbase+n] (+)= sum_k A[r][k] * Wsub[n*TOTAL + k]
// BM=128, BN=64, BK=16, 256 threads, 8x4 microtile; acc = 4 m-pairs x 4 n.
// ---------------------------------------------------------------------------
#define BM 128
#define BN 64
#define BK 16
#define AS 132
#define BS 68

__global__ void __launch_bounds__(256)
gemm_kernel(const float* __restrict__ Aparam, int lda,
            const float* __restrict__ Wsub,
            int jbase, int kc, int accum, int asel)
{
    __shared__ float As[BK * AS];
    __shared__ float Bs[BK * BS];

    const float* A = asel ? g_h : Aparam;

    int m0 = blockIdx.x * BM;
    int n0 = blockIdx.y * BN;
    int tid = threadIdx.x;
    int tx = tid & 15;          // n dir: 4 cols each
    int ty = tid >> 4;          // m dir: 8 rows each

    int a_r = tid >> 1;           // 0..127
    int a_k = (tid & 1) * 8;      // 0 or 8
    int b_r = tid >> 2;           // 0..63
    int b_k = (tid & 3) * 4;      // 0,4,8,12

    // acc2[i][j]: packed pair = rows (ty*8+2i, ty*8+2i+1), col tx*4+j
    unsigned long long acc2[4][4];
#pragma unroll
    for (int i = 0; i < 4; i++)
#pragma unroll
        for (int j = 0; j < 4; j++) acc2[i][j] = 0ull;

    for (int kk = 0; kk < kc; kk += BK) {
        float4 a0 = *(const float4*)(A + (size_t)(m0 + a_r) * lda + kk + a_k);
        float4 a1 = *(const float4*)(A + (size_t)(m0 + a_r) * lda + kk + a_k + 4);
        As[(a_k + 0) * AS + a_r] = a0.x;
        As[(a_k + 1) * AS + a_r] = a0.y;
        As[(a_k + 2) * AS + a_r] = a0.z;
        As[(a_k + 3) * AS + a_r] = a0.w;
        As[(a_k + 4) * AS + a_r] = a1.x;
        As[(a_k + 5) * AS + a_r] = a1.y;
        As[(a_k + 6) * AS + a_r] = a1.z;
        As[(a_k + 7) * AS + a_r] = a1.w;

        float4 bv = *(const float4*)(Wsub + (size_t)(n0 + b_r) * TOTAL + kk + b_k);
        Bs[(b_k + 0) * BS + b_r] = bv.x;
        Bs[(b_k + 1) * BS + b_r] = bv.y;
        Bs[(b_k + 2) * BS + b_r] = bv.z;
        Bs[(b_k + 3) * BS + b_r] = bv.w;

        __syncthreads();

#pragma unroll
        for (int k = 0; k < BK; k++) {
            float a[8], b[4];
            *(float4*)&a[0] = *(const float4*)&As[k * AS + ty * 8];
            *(float4*)&a[4] = *(const float4*)&As[k * AS + ty * 8 + 4];
            *(float4*)&b[0] = *(const float4*)&Bs[k * BS + tx * 4];

            unsigned long long ap[4], bb[4];
#pragma unroll
            for (int i = 0; i < 4; i++)
                asm("mov.b64 %0, {%1, %2};"
                    : "=l"(ap[i]) : "f"(a[2 * i]), "f"(a[2 * i + 1]));
#pragma unroll
            for (int j = 0; j < 4; j++)
                asm("mov.b64 %0, {%1, %2};"
                    : "=l"(bb[j]) : "f"(b[j]), "f"(b[j]));

#pragma unroll
            for (int i = 0; i < 4; i++)
#pragma unroll
                for (int j = 0; j < 4; j++)
                    asm("fma.rn.f32x2 %0, %1, %2, %0;"
                        : "+l"(acc2[i][j]) : "l"(ap[i]), "l"(bb[j]));
        }
        __syncthreads();
    }

#pragma unroll
    for (int i = 0; i < 4; i++) {
        float v0[4], v1[4];
#pragma unroll
        for (int j = 0; j < 4; j++)
            asm("mov.b64 {%0, %1}, %2;"
                : "=f"(v0[j]), "=f"(v1[j]) : "l"(acc2[i][j]));

        float* c0 = g_pre + (size_t)(m0 + ty * 8 + 2 * i) * NN + jbase + n0 + tx * 4;
        float* c1 = c0 + NN;
        if (accum) {
#pragma unroll
            for (int j = 0; j < 4; j++) { c0[j] += v0[j]; c1[j] += v1[j]; }
        } else {
            float4 w0, w1;
            w0.x = v0[0]; w0.y = v0[1]; w0.z = v0[2]; w0.w = v0[3];
            w1.x = v1[0]; w1.y = v1[1]; w1.z = v1[2]; w1.w = v1[3];
            *(float4*)c0 = w0;
            *(float4*)c1 = w1;
        }
    }
}

// ---------------------------------------------------------------------------
// In-block sequential recurrence, v5: 32 CTAs x 512 threads, one warp per
// row. Pure dependency-chain bound; chain trimmed by tracking z = p*2log2e
// with PRE-SCALED weights in smem (removes the FMUL before EX2):
//   chain: FMA(z+=h*wc) -> EX2 -> FADD -> RCP -> FMA(h) -> SHFL  ~90 cyc.
// tanh(p) = 1 - 2/(exp2(z)+1); exact at +/-inf.
// smem ws[i*129+t] = W*2log2e, zeroed at t>=i -> unconditional FMAs.
// ---------------------------------------------------------------------------
#define C2LOG2E 2.8853900817779268f

__global__ void __launch_bounds__(512, 1)
seq_kernel(const float* __restrict__ W, float* __restrict__ out, int b)
{
    extern __shared__ float ws[];  // 128*129 floats = 66048 B

    int tid  = threadIdx.x;        // 512
    int lane = tid & 31;
    int row  = blockIdx.x * 16 + (tid >> 5);
    int j0   = b * KB;

    // Stage triangular tile, pre-scaled by 2*log2(e); zero t >= i.
    {
        const float* Wt = W + (size_t)j0 * TOTAL + IN + j0;
#pragma unroll
        for (int ii = 0; ii < 32; ii++) {
            int idx = tid + ii * 512;
            int i = idx >> 7;
            int t = idx & 127;
            float v = Wt[(size_t)i * TOTAL + t] * C2LOG2E;
            ws[i * 129 + t] = (t < i) ? v : 0.0f;
        }
    }
    __syncthreads();

    float z[4];
#pragma unroll
    for (int q = 0; q < 4; q++)
        z[q] = g_pre[(size_t)row * NN + j0 + lane + 32 * q] * C2LOG2E;

    const float* wbase = ws + lane * 129;   // + q*32*129 + t

#pragma unroll
    for (int slot = 0; slot < 4; slot++) {
#pragma unroll
        for (int t2 = 0; t2 < 32; t2++) {
            int t = slot * 32 + t2;

            float e;  asm("ex2.approx.f32 %0, %1;" : "=f"(e) : "f"(z[slot]));
            float d = e + 1.0f;
            float r;  asm("rcp.approx.f32 %0, %1;" : "=f"(r) : "f"(d));
            float hv = fmaf(-2.0f, r, 1.0f);

            float h = __shfl_sync(0xffffffffu, hv, t2);

#pragma unroll
            for (int q = slot; q < 4; q++)
                z[q] = fmaf(h, wbase[q * 32 * 129 + t], z[q]);
        }
    }

    // Finalize: z[q] holds the final scaled preactivation of node lane+32q.
    const bool isOut = (b == NBLK - 1);
    if (!isOut) {
        float* ghrow = g_h + (size_t)row * KB;
#pragma unroll
        for (int q = 0; q < 4; q++) {
            float e;  asm("ex2.approx.f32 %0, %1;" : "=f"(e) : "f"(z[q]));
            float d = e + 1.0f;
            float r;  asm("rcp.approx.f32 %0, %1;" : "=f"(r) : "f"(d));
            ghrow[q * 32 + lane] = fmaf(-2.0f, r, 1.0f);
        }
    } else {
        float* orow = out + (size_t)row * OUT_N;
#pragma unroll
        for (int q = 0; q < 4; q++) {
            float e;  asm("ex2.approx.f32 %0, %1;" : "=f"(e) : "f"(z[q]));
            float d = e + 1.0f;
            float r;  asm("rcp.approx.f32 %0, %1;" : "=f"(r) : "f"(d));
            float h = fmaf(-2.0f, r, 1.0f);
            orow[q * 32 + lane] = 1.0f / (1.0f + __expf(-h));
        }
    }
}

// ---------------------------------------------------------------------------
extern "C" void kernel_launch(void* const* d_in, const int* in_sizes, int n_in,
                              void* d_out, int out_size)
{
    const float* x = (const float*)d_in[0];   // [512][1024]
    const float* W = (const float*)d_in[1];   // [4224][5248]
    float* out = (float*)d_out;               // [512][128]

    (void)in_sizes; (void)n_in; (void)out_size;

    cudaFuncSetAttribute(seq_kernel,
                         cudaFuncAttributeMaxDynamicSharedMemorySize, 66048);

    // Phase A: pre = x @ W[:, :1024]^T    (writes all of g_pre)
    gemm_kernel<<<dim3(B / BM, NN / BN), 256>>>(x, IN, W, /*jbase=*/0,
                                                /*kc=*/IN, /*accum=*/0,
                                                /*asel=*/0);

    for (int b = 0; b < NBLK; b++) {
        seq_kernel<<<32, 512, 66048>>>(W, out, b);

        if (b < NBLK - 1) {
            int jbase = (b + 1) * KB;
            int nrem  = NN - jbase;               // multiple of 128
            const float* Wsub = W + (size_t)jbase * TOTAL + (IN + b * KB);
            gemm_kernel<<<dim3(B / BM, nrem / BN), 256>>>(nullptr, KB, Wsub,
                                                          jbase, KB,
                                                          /*accum=*/1,
                                                          /*asel=*/1);
        }
    }
}